// round 16
// baseline (speedup 1.0000x reference)
#include <cuda_runtime.h>
#include <cuda_bf16.h>
#include <math.h>
#include <stdint.h>

// ---------------------------------------------------------------------------
// Problem constants
// ---------------------------------------------------------------------------
#define BATCH   4
#define SEQ     2048
#define DIN     4096
#define DPROJ   512
#define DMEM    512
#define ASSIST  512
#define RUN     1536
#define ROWS    (BATCH*SEQ)   // 8192

// ---------------------------------------------------------------------------
// Device scratch
// ---------------------------------------------------------------------------
__device__ float g_Q[(size_t)ROWS*DPROJ];     // reused: Q bf16 hi/lo
__device__ float g_K[(size_t)ROWS*DPROJ];     // reused: K bf16 hi/lo
__device__ float g_S[(size_t)BATCH*SEQ*SEQ];
__device__ float g_feat[(size_t)ROWS*DPROJ];
__device__ float g_Gz[(size_t)BATCH*RUN*DMEM];
__device__ float g_Gr[(size_t)BATCH*RUN*DMEM];
__device__ float g_Gh[(size_t)BATCH*RUN*DMEM];
__device__ float g_h[BATCH*DMEM];

// bf16 split operands
__device__ __nv_bfloat16 g_xhi[(size_t)ROWS*DIN];   // x hi; later feat hi
__device__ __nv_bfloat16 g_xlo[(size_t)ROWS*DIN];   // x lo; later feat lo
__device__ __nv_bfloat16 g_Whi[3][(size_t)DIN*DPROJ];
__device__ __nv_bfloat16 g_Wlo[3][(size_t)DIN*DPROJ];
__device__ __nv_bfloat16 g_Phi[(size_t)BATCH*SEQ*SEQ];
__device__ __nv_bfloat16 g_Plo[(size_t)BATCH*SEQ*SEQ];
__device__ __nv_bfloat16 g_Vh[(size_t)ROWS*DPROJ];
__device__ __nv_bfloat16 g_Vl[(size_t)ROWS*DPROJ];
__device__ __nv_bfloat16 g_Uwh[3][(size_t)DPROJ*DMEM];
__device__ __nv_bfloat16 g_Uwl[3][(size_t)DPROJ*DMEM];

// ---------------------------------------------------------------------------
// Split fp32 -> (hi, lo) bf16.  (only used for raw inputs now)
// ---------------------------------------------------------------------------
__global__ void split_kernel(const float* __restrict__ src,
                             __nv_bfloat16* __restrict__ hi,
                             __nv_bfloat16* __restrict__ lo, size_t n4)
{
    size_t i = (size_t)blockIdx.x * blockDim.x + threadIdx.x;
    size_t stride = (size_t)gridDim.x * blockDim.x;
    for (; i < n4; i += stride) {
        float4 v = ((const float4*)src)[i];
        __nv_bfloat16 h0 = __float2bfloat16(v.x);
        __nv_bfloat16 h1 = __float2bfloat16(v.y);
        __nv_bfloat16 h2 = __float2bfloat16(v.z);
        __nv_bfloat16 h3 = __float2bfloat16(v.w);
        __nv_bfloat162 hh0 = {h0, h1}, hh1 = {h2, h3};
        __nv_bfloat162 ll0 = {__float2bfloat16(v.x - __bfloat162float(h0)),
                              __float2bfloat16(v.y - __bfloat162float(h1))};
        __nv_bfloat162 ll1 = {__float2bfloat16(v.z - __bfloat162float(h2)),
                              __float2bfloat16(v.w - __bfloat162float(h3))};
        ((__nv_bfloat162*)hi)[i * 2]     = hh0;
        ((__nv_bfloat162*)hi)[i * 2 + 1] = hh1;
        ((__nv_bfloat162*)lo)[i * 2]     = ll0;
        ((__nv_bfloat162*)lo)[i * 2 + 1] = ll1;
    }
}

// ---------------------------------------------------------------------------
// MMA helpers
// ---------------------------------------------------------------------------
__device__ __forceinline__ uint32_t smem_addr_u32(const void* p) {
    uint32_t a;
    asm("{ .reg .u64 t; cvta.to.shared.u64 t, %1; cvt.u32.u64 %0, t; }"
        : "=r"(a) : "l"(p));
    return a;
}
__device__ __forceinline__ void ldsm_x4(uint32_t& r0, uint32_t& r1,
                                        uint32_t& r2, uint32_t& r3, uint32_t a) {
    asm volatile("ldmatrix.sync.aligned.m8n8.x4.shared.b16 {%0,%1,%2,%3}, [%4];"
                 : "=r"(r0), "=r"(r1), "=r"(r2), "=r"(r3) : "r"(a));
}
__device__ __forceinline__ void ldsm_x4_t(uint32_t& r0, uint32_t& r1,
                                          uint32_t& r2, uint32_t& r3, uint32_t a) {
    asm volatile("ldmatrix.sync.aligned.m8n8.x4.trans.shared.b16 {%0,%1,%2,%3}, [%4];"
                 : "=r"(r0), "=r"(r1), "=r"(r2), "=r"(r3) : "r"(a));
}
__device__ __forceinline__ void mma_bf16(float* d, const uint32_t* a,
                                         uint32_t b0, uint32_t b1) {
    asm volatile(
        "mma.sync.aligned.m16n8k16.row.col.f32.bf16.bf16.f32 "
        "{%0,%1,%2,%3}, {%4,%5,%6,%7}, {%8,%9}, {%0,%1,%2,%3};"
        : "+f"(d[0]), "+f"(d[1]), "+f"(d[2]), "+f"(d[3])
        : "r"(a[0]), "r"(a[1]), "r"(a[2]), "r"(a[3]), "r"(b0), "r"(b1));
}
__device__ __forceinline__ __nv_bfloat162 split_pair(float a, float b,
                                                     __nv_bfloat162& lo2) {
    __nv_bfloat16 ha = __float2bfloat16(a);
    __nv_bfloat16 hb = __float2bfloat16(b);
    lo2.x = __float2bfloat16(a - __bfloat162float(ha));
    lo2.y = __float2bfloat16(b - __bfloat162float(hb));
    __nv_bfloat162 hi2; hi2.x = ha; hi2.y = hb;
    return hi2;
}

#define APITCH 40
#define BPITCH 136
#define SM_AHI 0
#define SM_ALO 20480
#define SM_BHI 40960
#define SM_BLO 58368
#define QKV_SMEM 75776

// ---------------------------------------------------------------------------
// Generalized batched bf16x3 GEMM with fused-split epilogue:
//   C fp32 (optional) and/or (Chi, Clo) bf16 hi/lo (optional).
//   mode2: Kend = min(rowBase+128, K) for lower-triangular A (PV).
// ---------------------------------------------------------------------------
__global__ void __launch_bounds__(256) mma_gemm_gen(
    const __nv_bfloat16* __restrict__ Ah, const __nv_bfloat16* __restrict__ Al,
    const __nv_bfloat16* __restrict__ Bh, const __nv_bfloat16* __restrict__ Bl,
    const float* __restrict__ bias, float* __restrict__ C,
    __nv_bfloat16* __restrict__ Chi, __nv_bfloat16* __restrict__ Clo,
    int N, int K,
    size_t aStride, size_t bStride, size_t cStride, int mode2)
{
    extern __shared__ char smem[];
    int tid = threadIdx.x, lane = tid & 31, warp = tid >> 5;
    int bz = blockIdx.z;
    int rowBase = blockIdx.y * 128, colBase = blockIdx.x * 128;
    int Kend = K;
    if (mode2) Kend = (rowBase + 128 < K) ? rowBase + 128 : K;
    int warp_m = (warp >> 1) * 32, warp_n = (warp & 1) * 64;

    Ah += aStride * (size_t)bz;  Al += aStride * (size_t)bz;
    Bh += bStride * (size_t)bz;  Bl += bStride * (size_t)bz;
    if (C)   C   += cStride * (size_t)bz;
    if (Chi) { Chi += cStride * (size_t)bz; Clo += cStride * (size_t)bz; }

    uint32_t sA = smem_addr_u32(smem);
    uint32_t sAhi = sA + SM_AHI, sAlo = sA + SM_ALO;
    uint32_t sBhi = sA + SM_BHI, sBlo = sA + SM_BLO;

    int q = lane >> 3, r = lane & 7;
    int a_row[2];
    a_row[0] = warp_m + (q & 1) * 8 + r;
    a_row[1] = a_row[0] + 16;
    int a_col = (q >> 1) * 8;
    int b_k = (q & 1) * 8 + r;
    int b_n[4];
#pragma unroll
    for (int p = 0; p < 4; p++) b_n[p] = warp_n + p * 16 + (q >> 1) * 8;

    int a_ch0 = tid, a_ch1 = tid + 256;
    int ar0 = a_ch0 >> 2, as0 = a_ch0 & 3, ar1 = a_ch1 >> 2, as1 = a_ch1 & 3;
    int bk0 = a_ch0 >> 4, bs0 = a_ch0 & 15, bk1 = a_ch1 >> 4, bs1 = a_ch1 & 15;

    const __nv_bfloat16* Ahp0 = Ah + (size_t)(rowBase + ar0) * K + as0 * 8;
    const __nv_bfloat16* Ahp1 = Ah + (size_t)(rowBase + ar1) * K + as1 * 8;
    const __nv_bfloat16* Alp0 = Al + (size_t)(rowBase + ar0) * K + as0 * 8;
    const __nv_bfloat16* Alp1 = Al + (size_t)(rowBase + ar1) * K + as1 * 8;
    const __nv_bfloat16* Bhp0 = Bh + (size_t)bk0 * N + colBase + bs0 * 8;
    const __nv_bfloat16* Bhp1 = Bh + (size_t)bk1 * N + colBase + bs1 * 8;
    const __nv_bfloat16* Blp0 = Bl + (size_t)bk0 * N + colBase + bs0 * 8;
    const __nv_bfloat16* Blp1 = Bl + (size_t)bk1 * N + colBase + bs1 * 8;

    float acc[2][8][4];
#pragma unroll
    for (int i = 0; i < 2; i++)
#pragma unroll
        for (int j = 0; j < 8; j++)
#pragma unroll
            for (int v = 0; v < 4; v++) acc[i][j][v] = 0.0f;

    uint4 pah0, pah1, pal0, pal1, pbh0, pbh1, pbl0, pbl1;
    pah0 = *(const uint4*)(Ahp0); pah1 = *(const uint4*)(Ahp1);
    pal0 = *(const uint4*)(Alp0); pal1 = *(const uint4*)(Alp1);
    pbh0 = *(const uint4*)(Bhp0); pbh1 = *(const uint4*)(Bhp1);
    pbl0 = *(const uint4*)(Blp0); pbl1 = *(const uint4*)(Blp1);
    {
        char* base = (char*)smem;
        *(uint4*)(base + SM_AHI + (ar0 * APITCH + as0 * 8) * 2) = pah0;
        *(uint4*)(base + SM_AHI + (ar1 * APITCH + as1 * 8) * 2) = pah1;
        *(uint4*)(base + SM_ALO + (ar0 * APITCH + as0 * 8) * 2) = pal0;
        *(uint4*)(base + SM_ALO + (ar1 * APITCH + as1 * 8) * 2) = pal1;
        *(uint4*)(base + SM_BHI + (bk0 * BPITCH + bs0 * 8) * 2) = pbh0;
        *(uint4*)(base + SM_BHI + (bk1 * BPITCH + bs1 * 8) * 2) = pbh1;
        *(uint4*)(base + SM_BLO + (bk0 * BPITCH + bs0 * 8) * 2) = pbl0;
        *(uint4*)(base + SM_BLO + (bk1 * BPITCH + bs1 * 8) * 2) = pbl1;
    }
    __syncthreads();

    const int nTiles = Kend / 32;
    int buf = 0;
    for (int kt = 0; kt < nTiles; kt++) {
        bool nxt = (kt + 1 < nTiles);
        if (nxt) {
            int ko = (kt + 1) * 32;
            pah0 = *(const uint4*)(Ahp0 + ko); pah1 = *(const uint4*)(Ahp1 + ko);
            pal0 = *(const uint4*)(Alp0 + ko); pal1 = *(const uint4*)(Alp1 + ko);
            pbh0 = *(const uint4*)(Bhp0 + (size_t)ko * N);
            pbh1 = *(const uint4*)(Bhp1 + (size_t)ko * N);
            pbl0 = *(const uint4*)(Blp0 + (size_t)ko * N);
            pbl1 = *(const uint4*)(Blp1 + (size_t)ko * N);
        }

#pragma unroll
        for (int ks = 0; ks < 2; ks++) {
            uint32_t aoffh = sAhi + ((buf * 128) * APITCH + ks * 16 + a_col) * 2;
            uint32_t aoffl = sAlo + ((buf * 128) * APITCH + ks * 16 + a_col) * 2;
            uint32_t ahi[2][4], alo[2][4];
#pragma unroll
            for (int i = 0; i < 2; i++) {
                ldsm_x4(ahi[i][0], ahi[i][1], ahi[i][2], ahi[i][3],
                        aoffh + a_row[i] * (APITCH * 2));
                ldsm_x4(alo[i][0], alo[i][1], alo[i][2], alo[i][3],
                        aoffl + a_row[i] * (APITCH * 2));
            }
            uint32_t bhi[4][4], blo[4][4];
            uint32_t bkrow = (buf * 32 + ks * 16 + b_k) * (BPITCH * 2);
#pragma unroll
            for (int p = 0; p < 4; p++) {
                ldsm_x4_t(bhi[p][0], bhi[p][1], bhi[p][2], bhi[p][3],
                          sBhi + bkrow + b_n[p] * 2);
                ldsm_x4_t(blo[p][0], blo[p][1], blo[p][2], blo[p][3],
                          sBlo + bkrow + b_n[p] * 2);
            }
#pragma unroll
            for (int i = 0; i < 2; i++) {
#pragma unroll
                for (int p = 0; p < 4; p++) {
#pragma unroll
                    for (int t = 0; t < 2; t++) {
                        int j = p * 2 + t;
                        uint32_t b0h = bhi[p][t * 2], b1h = bhi[p][t * 2 + 1];
                        uint32_t b0l = blo[p][t * 2], b1l = blo[p][t * 2 + 1];
                        mma_bf16(acc[i][j], ahi[i], b0h, b1h);
                        mma_bf16(acc[i][j], ahi[i], b0l, b1l);
                        mma_bf16(acc[i][j], alo[i], b0h, b1h);
                    }
                }
            }
        }

        if (nxt) {
            int nb = buf ^ 1;
            char* base = (char*)smem;
            *(uint4*)(base + SM_AHI + ((nb * 128 + ar0) * APITCH + as0 * 8) * 2) = pah0;
            *(uint4*)(base + SM_AHI + ((nb * 128 + ar1) * APITCH + as1 * 8) * 2) = pah1;
            *(uint4*)(base + SM_ALO + ((nb * 128 + ar0) * APITCH + as0 * 8) * 2) = pal0;
            *(uint4*)(base + SM_ALO + ((nb * 128 + ar1) * APITCH + as1 * 8) * 2) = pal1;
            *(uint4*)(base + SM_BHI + ((nb * 32 + bk0) * BPITCH + bs0 * 8) * 2) = pbh0;
            *(uint4*)(base + SM_BHI + ((nb * 32 + bk1) * BPITCH + bs1 * 8) * 2) = pbh1;
            *(uint4*)(base + SM_BLO + ((nb * 32 + bk0) * BPITCH + bs0 * 8) * 2) = pbl0;
            *(uint4*)(base + SM_BLO + ((nb * 32 + bk1) * BPITCH + bs1 * 8) * 2) = pbl1;
        }
        __syncthreads();
        buf ^= 1;
    }

    int g = lane >> 2, tig = lane & 3;
#pragma unroll
    for (int i = 0; i < 2; i++) {
#pragma unroll
        for (int j = 0; j < 8; j++) {
            int col = colBase + warp_n + j * 8 + tig * 2;
            float2 bv = make_float2(0.f, 0.f);
            if (bias) bv = *(const float2*)(bias + col);
            int r0 = rowBase + warp_m + i * 16 + g;
            float2 o0 = make_float2(acc[i][j][0] + bv.x, acc[i][j][1] + bv.y);
            float2 o1 = make_float2(acc[i][j][2] + bv.x, acc[i][j][3] + bv.y);
            if (C) {
                *(float2*)(C + (size_t)r0 * N + col) = o0;
                *(float2*)(C + (size_t)(r0 + 8) * N + col) = o1;
            }
            if (Chi) {
                __nv_bfloat162 lo0, lo1;
                __nv_bfloat162 hi0 = split_pair(o0.x, o0.y, lo0);
                __nv_bfloat162 hi1 = split_pair(o1.x, o1.y, lo1);
                *(__nv_bfloat162*)(Chi + (size_t)r0 * N + col) = hi0;
                *(__nv_bfloat162*)(Clo + (size_t)r0 * N + col) = lo0;
                *(__nv_bfloat162*)(Chi + (size_t)(r0 + 8) * N + col) = hi1;
                *(__nv_bfloat162*)(Clo + (size_t)(r0 + 8) * N + col) = lo1;
            }
        }
    }
}

// ---------------------------------------------------------------------------
// Tensor-core scores GEMM (unchanged from R14/R15).
// ---------------------------------------------------------------------------
#define SC_APITCH 40
#define SC_AHI 0
#define SC_ALO 20480
#define SC_BHI 40960
#define SC_BLO 61440
#define SC_SMEM 81920

__global__ void __launch_bounds__(256) scores_mma_kernel(
    const __nv_bfloat16* __restrict__ Qh, const __nv_bfloat16* __restrict__ Ql,
    const __nv_bfloat16* __restrict__ Kh, const __nv_bfloat16* __restrict__ Kl,
    float* __restrict__ S)
{
    extern __shared__ char smem[];
    const int KD = DPROJ;
    int tid = threadIdx.x, lane = tid & 31, warp = tid >> 5;
    int bz = blockIdx.z;
    int rowBase = blockIdx.y * 128, colBase = blockIdx.x * 128;
    if (rowBase + 127 < colBase) return;
    int warp_m = (warp >> 1) * 32, warp_n = (warp & 1) * 64;

    uint32_t sA = smem_addr_u32(smem);
    uint32_t sAhi = sA + SC_AHI, sAlo = sA + SC_ALO;
    uint32_t sBhi = sA + SC_BHI, sBlo = sA + SC_BLO;

    int q = lane >> 3, r = lane & 7;
    int a_row[2];
    a_row[0] = warp_m + (q & 1) * 8 + r;
    a_row[1] = a_row[0] + 16;
    int a_col = (q >> 1) * 8;
    int b_row[4];
#pragma unroll
    for (int p = 0; p < 4; p++) b_row[p] = warp_n + p * 16 + (q & 1) * 8 + r;

    int ch0 = tid, ch1 = tid + 256;
    int ar0 = ch0 >> 2, as0 = ch0 & 3, ar1 = ch1 >> 2, as1 = ch1 & 3;

    size_t bbase = (size_t)bz * SEQ;
    const __nv_bfloat16* Ahp0 = Qh + (bbase + rowBase + ar0) * KD + as0 * 8;
    const __nv_bfloat16* Ahp1 = Qh + (bbase + rowBase + ar1) * KD + as1 * 8;
    const __nv_bfloat16* Alp0 = Ql + (bbase + rowBase + ar0) * KD + as0 * 8;
    const __nv_bfloat16* Alp1 = Ql + (bbase + rowBase + ar1) * KD + as1 * 8;
    const __nv_bfloat16* Bhp0 = Kh + (bbase + colBase + ar0) * KD + as0 * 8;
    const __nv_bfloat16* Bhp1 = Kh + (bbase + colBase + ar1) * KD + as1 * 8;
    const __nv_bfloat16* Blp0 = Kl + (bbase + colBase + ar0) * KD + as0 * 8;
    const __nv_bfloat16* Blp1 = Kl + (bbase + colBase + ar1) * KD + as1 * 8;

    float acc[2][8][4];
#pragma unroll
    for (int i = 0; i < 2; i++)
#pragma unroll
        for (int j = 0; j < 8; j++)
#pragma unroll
            for (int v = 0; v < 4; v++) acc[i][j][v] = 0.0f;

    uint4 pah0, pah1, pal0, pal1, pbh0, pbh1, pbl0, pbl1;
    pah0 = *(const uint4*)(Ahp0); pah1 = *(const uint4*)(Ahp1);
    pal0 = *(const uint4*)(Alp0); pal1 = *(const uint4*)(Alp1);
    pbh0 = *(const uint4*)(Bhp0); pbh1 = *(const uint4*)(Bhp1);
    pbl0 = *(const uint4*)(Blp0); pbl1 = *(const uint4*)(Blp1);
    {
        char* base = (char*)smem;
        *(uint4*)(base + SC_AHI + (ar0 * SC_APITCH + as0 * 8) * 2) = pah0;
        *(uint4*)(base + SC_AHI + (ar1 * SC_APITCH + as1 * 8) * 2) = pah1;
        *(uint4*)(base + SC_ALO + (ar0 * SC_APITCH + as0 * 8) * 2) = pal0;
        *(uint4*)(base + SC_ALO + (ar1 * SC_APITCH + as1 * 8) * 2) = pal1;
        *(uint4*)(base + SC_BHI + (ar0 * SC_APITCH + as0 * 8) * 2) = pbh0;
        *(uint4*)(base + SC_BHI + (ar1 * SC_APITCH + as1 * 8) * 2) = pbh1;
        *(uint4*)(base + SC_BLO + (ar0 * SC_APITCH + as0 * 8) * 2) = pbl0;
        *(uint4*)(base + SC_BLO + (ar1 * SC_APITCH + as1 * 8) * 2) = pbl1;
    }
    __syncthreads();

    const int nTiles = KD / 32;
    int buf = 0;
    for (int kt = 0; kt < nTiles; kt++) {
        bool nxt = (kt + 1 < nTiles);
        if (nxt) {
            int ko = (kt + 1) * 32;
            pah0 = *(const uint4*)(Ahp0 + ko); pah1 = *(const uint4*)(Ahp1 + ko);
            pal0 = *(const uint4*)(Alp0 + ko); pal1 = *(const uint4*)(Alp1 + ko);
            pbh0 = *(const uint4*)(Bhp0 + ko); pbh1 = *(const uint4*)(Bhp1 + ko);
            pbl0 = *(const uint4*)(Blp0 + ko); pbl1 = *(const uint4*)(Blp1 + ko);
        }

#pragma unroll
        for (int ks = 0; ks < 2; ks++) {
            uint32_t aoffh = sAhi + ((buf * 128) * SC_APITCH + ks * 16 + a_col) * 2;
            uint32_t aoffl = sAlo + ((buf * 128) * SC_APITCH + ks * 16 + a_col) * 2;
            uint32_t ahi[2][4], alo[2][4];
#pragma unroll
            for (int i = 0; i < 2; i++) {
                ldsm_x4(ahi[i][0], ahi[i][1], ahi[i][2], ahi[i][3],
                        aoffh + a_row[i] * (SC_APITCH * 2));
                ldsm_x4(alo[i][0], alo[i][1], alo[i][2], alo[i][3],
                        aoffl + a_row[i] * (SC_APITCH * 2));
            }
            uint32_t boffh = sBhi + ((buf * 128) * SC_APITCH + ks * 16 + a_col) * 2;
            uint32_t boffl = sBlo + ((buf * 128) * SC_APITCH + ks * 16 + a_col) * 2;
            uint32_t bhi[4][4], blo[4][4];
#pragma unroll
            for (int p = 0; p < 4; p++) {
                ldsm_x4(bhi[p][0], bhi[p][1], bhi[p][2], bhi[p][3],
                        boffh + b_row[p] * (SC_APITCH * 2));
                ldsm_x4(blo[p][0], blo[p][1], blo[p][2], blo[p][3],
                        boffl + b_row[p] * (SC_APITCH * 2));
            }
#pragma unroll
            for (int i = 0; i < 2; i++) {
#pragma unroll
                for (int p = 0; p < 4; p++) {
#pragma unroll
                    for (int t = 0; t < 2; t++) {
                        int j = p * 2 + t;
                        uint32_t b0h = bhi[p][t], b1h = bhi[p][t + 2];
                        uint32_t b0l = blo[p][t], b1l = blo[p][t + 2];
                        mma_bf16(acc[i][j], ahi[i], b0h, b1h);
                        mma_bf16(acc[i][j], ahi[i], b0l, b1l);
                        mma_bf16(acc[i][j], alo[i], b0h, b1h);
                    }
                }
            }
        }

        if (nxt) {
            int nb = buf ^ 1;
            char* base = (char*)smem;
            *(uint4*)(base + SC_AHI + ((nb * 128 + ar0) * SC_APITCH + as0 * 8) * 2) = pah0;
            *(uint4*)(base + SC_AHI + ((nb * 128 + ar1) * SC_APITCH + as1 * 8) * 2) = pah1;
            *(uint4*)(base + SC_ALO + ((nb * 128 + ar0) * SC_APITCH + as0 * 8) * 2) = pal0;
            *(uint4*)(base + SC_ALO + ((nb * 128 + ar1) * SC_APITCH + as1 * 8) * 2) = pal1;
            *(uint4*)(base + SC_BHI + ((nb * 128 + ar0) * SC_APITCH + as0 * 8) * 2) = pbh0;
            *(uint4*)(base + SC_BHI + ((nb * 128 + ar1) * SC_APITCH + as1 * 8) * 2) = pbh1;
            *(uint4*)(base + SC_BLO + ((nb * 128 + ar0) * SC_APITCH + as0 * 8) * 2) = pbl0;
            *(uint4*)(base + SC_BLO + ((nb * 128 + ar1) * SC_APITCH + as1 * 8) * 2) = pbl1;
        }
        __syncthreads();
        buf ^= 1;
    }

    float* Sb = S + (size_t)bz * SEQ * SEQ;
    int g = lane >> 2, tig = lane & 3;
#pragma unroll
    for (int i = 0; i < 2; i++) {
#pragma unroll
        for (int j = 0; j < 8; j++) {
            int col = colBase + warp_n + j * 8 + tig * 2;
            int r0 = rowBase + warp_m + i * 16 + g;
            *(float2*)(Sb + (size_t)r0 * SEQ + col) =
                make_float2(acc[i][j][0], acc[i][j][1]);
            *(float2*)(Sb + (size_t)(r0 + 8) * SEQ + col) =
                make_float2(acc[i][j][2], acc[i][j][3]);
        }
    }
}

// ---------------------------------------------------------------------------
// Causal row softmax: fp32 scores -> bf16 (hi, lo) probabilities.
// ---------------------------------------------------------------------------
__global__ void softmax_causal_kernel()
{
    int r = blockIdx.x, b = blockIdx.y;
    size_t rowoff = ((size_t)b * SEQ + r) * SEQ;
    const float* row = g_S + rowoff;
    int len = r + 1;
    int tid = threadIdx.x;
    __shared__ float buf[SEQ];
    __shared__ float red[256];
    const float inv = rsqrtf(512.0f);

    float m = -3.4e38f;
    for (int i = tid; i < len; i += 256) m = fmaxf(m, row[i]);
    red[tid] = m; __syncthreads();
    for (int s = 128; s; s >>= 1) { if (tid < s) red[tid] = fmaxf(red[tid], red[tid + s]); __syncthreads(); }
    m = red[0] * inv;
    __syncthreads();

    float ssum = 0.0f;
    for (int i = tid; i < len; i += 256) {
        float e = __expf(row[i] * inv - m);
        buf[i] = e;
        ssum += e;
    }
    red[tid] = ssum; __syncthreads();
    for (int s = 128; s; s >>= 1) { if (tid < s) red[tid] += red[tid + s]; __syncthreads(); }
    float denom = 1.0f / red[0];
    __syncthreads();

    for (int i = tid; i < SEQ; i += 256) {
        float v = (i < len) ? buf[i] * denom : 0.0f;
        __nv_bfloat16 hi = __float2bfloat16(v);
        __nv_bfloat16 lo = __float2bfloat16(v - __bfloat162float(hi));
        g_Phi[rowoff + i] = hi;
        g_Plo[rowoff + i] = lo;
    }
}

// ---------------------------------------------------------------------------
// Prefix pooling + h0 (reads fp32 feat).
// ---------------------------------------------------------------------------
__global__ void pool_kernel(const float* __restrict__ Wscore,
                            const float* __restrict__ Wp2h,
                            const float* __restrict__ bp2h)
{
    int b = blockIdx.x;
    const float* feat = g_feat + (size_t)b * SEQ * DPROJ;
    __shared__ float wsc[512];
    __shared__ float sc[512];
    __shared__ float pooled[512];
    __shared__ float red[256];
    int tid = threadIdx.x;

    for (int i = tid; i < 512; i += 256) wsc[i] = Wscore[i];
    __syncthreads();

    int w = tid >> 5, l = tid & 31;
    for (int u = w; u < ASSIST; u += 8) {
        float s = 0.0f;
        for (int p = l; p < DPROJ; p += 32)
            s = fmaf(feat[(size_t)u * DPROJ + p], wsc[p], s);
#pragma unroll
        for (int o = 16; o; o >>= 1) s += __shfl_xor_sync(0xffffffffu, s, o);
        if (l == 0) sc[u] = s;
    }
    __syncthreads();

    float m = fmaxf(sc[tid], sc[tid + 256]);
    red[tid] = m; __syncthreads();
    for (int s = 128; s; s >>= 1) { if (tid < s) red[tid] = fmaxf(red[tid], red[tid + s]); __syncthreads(); }
    m = red[0]; __syncthreads();

    float e0 = expf(sc[tid] - m), e1 = expf(sc[tid + 256] - m);
    red[tid] = e0 + e1; __syncthreads();
    for (int s = 128; s; s >>= 1) { if (tid < s) red[tid] += red[tid + s]; __syncthreads(); }
    float inv = 1.0f / red[0];
    __syncthreads();
    sc[tid] = e0 * inv; sc[tid + 256] = e1 * inv;
    __syncthreads();

    for (int p = tid; p < DPROJ; p += 256) {
        float acc = 0.0f;
        for (int u = 0; u < ASSIST; u++)
            acc = fmaf(sc[u], feat[(size_t)u * DPROJ + p], acc);
        pooled[p] = acc;
    }
    __syncthreads();

    for (int c = tid; c < DMEM; c += 256) {
        float acc = bp2h[c];
        for (int k = 0; k < DPROJ; k++)
            acc = fmaf(pooled[k], Wp2h[(size_t)k * DMEM + c], acc);
        g_h[b * DMEM + c] = tanhf(acc);
    }
}

__global__ void init_out_kernel(float* __restrict__ out, const float* __restrict__ bmem)
{
    int i = blockIdx.x * blockDim.x + threadIdx.x;
    if (i < BATCH * RUN) out[i] = bmem[0];
}

// ---------------------------------------------------------------------------
// Cluster-based sequential scan — EXACT R11 (best known).
// ---------------------------------------------------------------------------
#define SCAN_THREADS 512
#define CL 16

#define H_OFF    0
#define RH_OFF   2048
#define PART_OFF 4096
#define WM_OFF   8192
#define SCAN_SMEM 8320

__device__ __forceinline__ uint32_t mapa_rank(uint32_t saddr, uint32_t rank) {
    uint32_t r;
    asm("mapa.shared::cluster.u32 %0, %1, %2;" : "=r"(r) : "r"(saddr), "r"(rank));
    return r;
}
__device__ __forceinline__ void stc_f32(uint32_t addr, float v) {
    asm volatile("st.shared::cluster.f32 [%0], %1;" :: "r"(addr), "f"(v));
}
#define CLUSTER_SYNC() do { \
    asm volatile("barrier.cluster.arrive.aligned;" ::: "memory"); \
    asm volatile("barrier.cluster.wait.aligned;" ::: "memory"); \
} while (0)

__global__ void __launch_bounds__(SCAN_THREADS, 1) scan_cluster(
    const float* __restrict__ Uz, const float* __restrict__ Ur,
    const float* __restrict__ Uh, const float* __restrict__ Wmem,
    const float* __restrict__ Gz, const float* __restrict__ Gr,
    const float* __restrict__ Gh, float* __restrict__ out)
{
    extern __shared__ char smem[];
    float*  h_s  = (float*)(smem + H_OFF);
    float*  rh_s = (float*)(smem + RH_OFF);
    float2* part = (float2*)(smem + PART_OFF);
    float*  wm_s = (float*)(smem + WM_OFF);

    int tid = threadIdx.x;
    int c   = tid & 31;
    int seg = tid >> 5;
    int kbase = seg * 32;

    uint32_t rank;
    asm("mov.u32 %0, %%cluster_ctarank;" : "=r"(rank));
    int cg0 = (int)rank * 32;
    int gb  = blockIdx.x >> 4;

    float uz[32], ur[32], uh[32];
#pragma unroll
    for (int i = 0; i < 32; i++) {
        uz[i] = Uz[(size_t)(kbase + i) * DMEM + cg0 + c];
        ur[i] = Ur[(size_t)(kbase + i) * DMEM + cg0 + c];
        uh[i] = Uh[(size_t)(kbase + i) * DMEM + cg0 + c];
    }
    if (tid < 32) wm_s[tid] = Wmem[cg0 + tid];

    h_s[tid] = __ldcg(&g_h[(size_t)gb * DMEM + tid]);
    __syncthreads();

    uint32_t rh_base = smem_addr_u32(rh_s);
    uint32_t h_base  = smem_addr_u32(h_s);

    const float dtc = 1.0f / 1535.0f;
    float zreg = 0.0f;

    for (int t = 0; t < RUN; t++) {
        float dtv = (t == 0) ? 0.0f : dtc;

        float gA = 0.0f, gH = 0.0f;
        if (tid < 64) {
            int cc = tid & 31, mat = tid >> 5;
            const float* P = mat ? Gr : Gz;
            gA = __ldg(&P[((size_t)(gb * RUN + t)) * DMEM + cg0 + cc]);
        }
        if (tid < 32) {
            gH = __ldg(&Gh[((size_t)(gb * RUN + t)) * DMEM + cg0 + tid]);
        }

        float pz = 0.f, pr = 0.f;
        const float4* hp = (const float4*)&h_s[kbase];
#pragma unroll
        for (int i = 0; i < 8; i++) {
            float4 h4 = hp[i];
            pz = fmaf(h4.x, uz[4*i+0], pz); pr = fmaf(h4.x, ur[4*i+0], pr);
            pz = fmaf(h4.y, uz[4*i+1], pz); pr = fmaf(h4.y, ur[4*i+1], pr);
            pz = fmaf(h4.z, uz[4*i+2], pz); pr = fmaf(h4.z, ur[4*i+2], pr);
            pz = fmaf(h4.w, uz[4*i+3], pz); pr = fmaf(h4.w, ur[4*i+3], pr);
        }
        part[tid] = make_float2(pz, pr);
        __syncthreads();

        if (tid < 64) {
            int cc = tid & 31, mat = tid >> 5;
            float s = 0.0f;
#pragma unroll
            for (int sg = 0; sg < 16; sg++) {
                float2 p = part[sg * 32 + cc];
                s += mat ? p.y : p.x;
            }
            float v = gA + s;
            float sig = 1.0f / (1.0f + __expf(-v));
            if (mat == 0) {
                zreg = sig;
            } else {
                float rhv = sig * h_s[cg0 + cc];
                uint32_t a = rh_base + (uint32_t)(cg0 + cc) * 4u;
#pragma unroll
                for (int rk = 0; rk < CL; rk++)
                    stc_f32(mapa_rank(a, (uint32_t)rk), rhv);
            }
        }
        CLUSTER_SYNC();

        float ph = 0.f;
        const float4* rp = (const float4*)&rh_s[kbase];
#pragma unroll
        for (int i = 0; i < 8; i++) {
            float4 r4 = rp[i];
            ph = fmaf(r4.x, uh[4*i+0], ph);
            ph = fmaf(r4.y, uh[4*i+1], ph);
            ph = fmaf(r4.z, uh[4*i+2], ph);
            ph = fmaf(r4.w, uh[4*i+3], ph);
        }
        part[tid].x = ph;
        __syncthreads();

        if (tid < 32) {
            int cc = tid;
            float s = 0.0f;
#pragma unroll
            for (int sg = 0; sg < 16; sg++)
                s += part[sg * 32 + cc].x;
            float hh   = tanhf(gH + s);
            int   cg   = cg0 + cc;
            float hold = h_s[cg];
            float hnew = hold + zreg * (hh - hold);
            float hout = hnew + dtv * (hnew - hold);
            if (t < RUN - 1) {
                uint32_t a = h_base + (uint32_t)cg * 4u;
#pragma unroll
                for (int rk = 0; rk < CL; rk++)
                    stc_f32(mapa_rank(a, (uint32_t)rk), hout);
            }
            float lv = hout * wm_s[cc];
#pragma unroll
            for (int o = 16; o; o >>= 1)
                lv += __shfl_xor_sync(0xffffffffu, lv, o);
            if (cc == 0)
                atomicAdd(&out[gb * RUN + t], lv);
        }
        CLUSTER_SYNC();
    }
}

// ---------------------------------------------------------------------------
// Host
// ---------------------------------------------------------------------------
extern "C" void kernel_launch(void* const* d_in, const int* in_sizes, int n_in,
                              void* d_out, int out_size)
{
    const float* x      = (const float*)d_in[0];
    const float* Wq     = (const float*)d_in[1];
    const float* bq     = (const float*)d_in[2];
    const float* Wk     = (const float*)d_in[3];
    const float* bk     = (const float*)d_in[4];
    const float* Wv     = (const float*)d_in[5];
    const float* bv     = (const float*)d_in[6];
    const float* Wz     = (const float*)d_in[7];
    const float* Uz     = (const float*)d_in[8];
    const float* bz     = (const float*)d_in[9];
    const float* Wr     = (const float*)d_in[10];
    const float* Ur     = (const float*)d_in[11];
    const float* br     = (const float*)d_in[12];
    const float* Wh     = (const float*)d_in[13];
    const float* Uh     = (const float*)d_in[14];
    const float* bh     = (const float*)d_in[15];
    const float* Wmem   = (const float*)d_in[16];
    const float* bmem   = (const float*)d_in[17];
    const float* Wp2h   = (const float*)d_in[18];
    const float* bp2h   = (const float*)d_in[19];
    const float* Wscore = (const float*)d_in[20];
    (void)in_sizes; (void)n_in;
    float* out = (float*)d_out;

    float *pQbuf, *pKbuf, *pS, *pF, *pGz, *pGr, *pGh;
    cudaGetSymbolAddress((void**)&pQbuf, g_Q);
    cudaGetSymbolAddress((void**)&pKbuf, g_K);
    cudaGetSymbolAddress((void**)&pS,  g_S);
    cudaGetSymbolAddress((void**)&pF,  g_feat);
    cudaGetSymbolAddress((void**)&pGz, g_Gz);
    cudaGetSymbolAddress((void**)&pGr, g_Gr);
    cudaGetSymbolAddress((void**)&pGh, g_Gh);

    __nv_bfloat16 *pxh, *pxl, *pWh, *pWl, *pPhi, *pPlo, *pVh, *pVl,
                  *pUwh, *pUwl;
    cudaGetSymbolAddress((void**)&pxh,  g_xhi);
    cudaGetSymbolAddress((void**)&pxl,  g_xlo);
    cudaGetSymbolAddress((void**)&pWh,  g_Whi);
    cudaGetSymbolAddress((void**)&pWl,  g_Wlo);
    cudaGetSymbolAddress((void**)&pPhi, g_Phi);
    cudaGetSymbolAddress((void**)&pPlo, g_Plo);
    cudaGetSymbolAddress((void**)&pVh,  g_Vh);
    cudaGetSymbolAddress((void**)&pVl,  g_Vl);
    cudaGetSymbolAddress((void**)&pUwh, g_Uwh);
    cudaGetSymbolAddress((void**)&pUwl, g_Uwl);

    dim3 t256(256);
    const size_t WSZ  = (size_t)DIN * DPROJ;
    const size_t QKSZ = (size_t)ROWS * DPROJ;   // 4M
    const size_t UWSZ = (size_t)DPROJ * DMEM;   // 256K

    cudaFuncSetAttribute(mma_gemm_gen,
                         cudaFuncAttributeMaxDynamicSharedMemorySize, QKV_SMEM);
    cudaFuncSetAttribute(scores_mma_kernel,
                         cudaFuncAttributeMaxDynamicSharedMemorySize, SC_SMEM);

    // split x and W into bf16 (hi, lo)
    split_kernel<<<2048, t256>>>(x,  pxh, pxl, (size_t)ROWS * DIN / 4);
    split_kernel<<<512,  t256>>>(Wq, pWh,           pWl,           WSZ / 4);
    split_kernel<<<512,  t256>>>(Wk, pWh + WSZ,     pWl + WSZ,     WSZ / 4);
    split_kernel<<<512,  t256>>>(Wv, pWh + 2 * WSZ, pWl + 2 * WSZ, WSZ / 4);

    // Q/K bf16 hi/lo live in the (dead) fp32 g_Q / g_K buffers
    __nv_bfloat16* pQh = (__nv_bfloat16*)pQbuf;
    __nv_bfloat16* pQl = (__nv_bfloat16*)pQbuf + QKSZ;
    __nv_bfloat16* pKh = (__nv_bfloat16*)pKbuf;
    __nv_bfloat16* pKl = (__nv_bfloat16*)pKbuf + QKSZ;

    // QKV projections (tensor cores) -> bf16 hi/lo outputs directly
    {
        dim3 g(DPROJ / 128, ROWS / 128, 1);
        mma_gemm_gen<<<g, t256, QKV_SMEM>>>(pxh, pxl, pWh,           pWl,           bq,
                                            nullptr, pQh, pQl, DPROJ, DIN, 0, 0, 0, 0);
        mma_gemm_gen<<<g, t256, QKV_SMEM>>>(pxh, pxl, pWh + WSZ,     pWl + WSZ,     bk,
                                            nullptr, pKh, pKl, DPROJ, DIN, 0, 0, 0, 0);
        mma_gemm_gen<<<g, t256, QKV_SMEM>>>(pxh, pxl, pWh + 2 * WSZ, pWl + 2 * WSZ, bv,
                                            nullptr, pVh, pVl, DPROJ, DIN, 0, 0, 0, 0);
    }

    // scores = Q K^T (tensor cores, causal tile skip)
    {
        dim3 g(SEQ / 128, SEQ / 128, BATCH);
        scores_mma_kernel<<<g, t256, SC_SMEM>>>(pQh, pQl, pKh, pKl, pS);
    }

    // softmax -> bf16 (hi, lo) probabilities
    softmax_causal_kernel<<<dim3(SEQ, BATCH), t256>>>();

    // feat = P V (tensor cores): fp32 for pool + bf16 hi/lo for G*
    // (x splits are dead now; their buffers hold feat hi/lo)
    {
        dim3 g(DPROJ / 128, SEQ / 128, BATCH);
        mma_gemm_gen<<<g, t256, QKV_SMEM>>>(pPhi, pPlo, pVh, pVl, nullptr,
                                            pF, pxh, pxl,
                                            DPROJ, SEQ,
                                            (size_t)SEQ * SEQ,
                                            (size_t)SEQ * DPROJ,
                                            (size_t)SEQ * DPROJ, 1);
    }

    pool_kernel<<<BATCH, t256>>>(Wscore, Wp2h, bp2h);

    // split Wz/Wr/Wh
    split_kernel<<<256, t256>>>(Wz, pUwh,            pUwl,            UWSZ / 4);
    split_kernel<<<256, t256>>>(Wr, pUwh + UWSZ,     pUwl + UWSZ,     UWSZ / 4);
    split_kernel<<<256, t256>>>(Wh, pUwh + 2 * UWSZ, pUwl + 2 * UWSZ, UWSZ / 4);

    // G* = feat_assist @ W* + b* (feat hi/lo at assist offset, full-seq stride)
    {
        dim3 g(DMEM / 128, RUN / 128, BATCH);
        const __nv_bfloat16* fAh = pxh + (size_t)ASSIST * DPROJ;
        const __nv_bfloat16* fAl = pxl + (size_t)ASSIST * DPROJ;
        size_t aS = (size_t)SEQ * DPROJ, cS = (size_t)RUN * DMEM;
        mma_gemm_gen<<<g, t256, QKV_SMEM>>>(fAh, fAl, pUwh,            pUwl,            bz,
                                            pGz, nullptr, nullptr, DMEM, DPROJ, aS, 0, cS, 0);
        mma_gemm_gen<<<g, t256, QKV_SMEM>>>(fAh, fAl, pUwh + UWSZ,     pUwl + UWSZ,     br,
                                            pGr, nullptr, nullptr, DMEM, DPROJ, aS, 0, cS, 0);
        mma_gemm_gen<<<g, t256, QKV_SMEM>>>(fAh, fAl, pUwh + 2 * UWSZ, pUwl + 2 * UWSZ, bh,
                                            pGh, nullptr, nullptr, DMEM, DPROJ, aS, 0, cS, 0);
    }

    init_out_kernel<<<(BATCH * RUN + 255) / 256, t256>>>(out, bmem);

    // cluster scan: 4 clusters x 16 CTAs x 512 threads
    cudaFuncSetAttribute(scan_cluster,
                         cudaFuncAttributeMaxDynamicSharedMemorySize, SCAN_SMEM);
    cudaFuncSetAttribute(scan_cluster,
                         cudaFuncAttributeNonPortableClusterSizeAllowed, 1);
    {
        cudaLaunchConfig_t cfg = {};
        cfg.gridDim  = dim3(64, 1, 1);
        cfg.blockDim = dim3(SCAN_THREADS, 1, 1);
        cfg.dynamicSmemBytes = SCAN_SMEM;
        cfg.stream = 0;
        cudaLaunchAttribute attrs[1];
        attrs[0].id = cudaLaunchAttributeClusterDimension;
        attrs[0].val.clusterDim.x = CL;
        attrs[0].val.clusterDim.y = 1;
        attrs[0].val.clusterDim.z = 1;
        cfg.attrs = attrs;
        cfg.numAttrs = 1;
        cudaLaunchKernelEx(&cfg, scan_cluster,
                           Uz, Ur, Uh, Wmem,
                           (const float*)pGz, (const float*)pGr,
                           (const float*)pGh, out);
    }

    (void)out_size;
}

// round 17
// speedup vs baseline: 1.0352x; 1.0352x over previous
#include <cuda_runtime.h>
#include <cuda_bf16.h>
#include <math.h>
#include <stdint.h>

// ---------------------------------------------------------------------------
// Problem constants
// ---------------------------------------------------------------------------
#define BATCH   4
#define SEQ     2048
#define DIN     4096
#define DPROJ   512
#define DMEM    512
#define ASSIST  512
#define RUN     1536
#define ROWS    (BATCH*SEQ)   // 8192
#define NG      1536          // combined G width (z|r|h)

// ---------------------------------------------------------------------------
// Device scratch
// ---------------------------------------------------------------------------
__device__ float g_Q[(size_t)ROWS*DPROJ];
__device__ float g_K[(size_t)ROWS*DPROJ];
__device__ float g_V[(size_t)ROWS*DPROJ];
__device__ float g_S[(size_t)BATCH*SEQ*SEQ];
__device__ float g_feat[(size_t)ROWS*DPROJ];
__device__ float g_G[(size_t)BATCH*RUN*NG];       // combined Gz|Gr|Gh
__device__ float g_h[BATCH*DMEM];
__device__ float g_bzrh[NG];

// bf16 split operands
__device__ __nv_bfloat16 g_xhi[(size_t)ROWS*DIN];
__device__ __nv_bfloat16 g_xlo[(size_t)ROWS*DIN];
__device__ __nv_bfloat16 g_Whi[3][(size_t)DIN*DPROJ];
__device__ __nv_bfloat16 g_Wlo[3][(size_t)DIN*DPROJ];
__device__ __nv_bfloat16 g_Phi[(size_t)BATCH*SEQ*SEQ];
__device__ __nv_bfloat16 g_Plo[(size_t)BATCH*SEQ*SEQ];
__device__ __nv_bfloat16 g_Vh[(size_t)ROWS*DPROJ];
__device__ __nv_bfloat16 g_Vl[(size_t)ROWS*DPROJ];
__device__ __nv_bfloat16 g_fah[(size_t)BATCH*RUN*DMEM];
__device__ __nv_bfloat16 g_fal[(size_t)BATCH*RUN*DMEM];
__device__ __nv_bfloat16 g_UwCh[(size_t)DPROJ*NG];   // Wz|Wr|Wh combined, hi
__device__ __nv_bfloat16 g_UwCl[(size_t)DPROJ*NG];   // lo

// ---------------------------------------------------------------------------
// Split fp32 -> (hi, lo) bf16 (contiguous dst).
// ---------------------------------------------------------------------------
__global__ void split_kernel(const float* __restrict__ src,
                             __nv_bfloat16* __restrict__ hi,
                             __nv_bfloat16* __restrict__ lo, size_t n4)
{
    size_t i = (size_t)blockIdx.x * blockDim.x + threadIdx.x;
    size_t stride = (size_t)gridDim.x * blockDim.x;
    for (; i < n4; i += stride) {
        float4 v = ((const float4*)src)[i];
        __nv_bfloat16 h0 = __float2bfloat16(v.x);
        __nv_bfloat16 h1 = __float2bfloat16(v.y);
        __nv_bfloat16 h2 = __float2bfloat16(v.z);
        __nv_bfloat16 h3 = __float2bfloat16(v.w);
        __nv_bfloat162 hh0 = {h0, h1}, hh1 = {h2, h3};
        __nv_bfloat162 ll0 = {__float2bfloat16(v.x - __bfloat162float(h0)),
                              __float2bfloat16(v.y - __bfloat162float(h1))};
        __nv_bfloat162 ll1 = {__float2bfloat16(v.z - __bfloat162float(h2)),
                              __float2bfloat16(v.w - __bfloat162float(h3))};
        ((__nv_bfloat162*)hi)[i * 2]     = hh0;
        ((__nv_bfloat162*)hi)[i * 2 + 1] = hh1;
        ((__nv_bfloat162*)lo)[i * 2]     = ll0;
        ((__nv_bfloat162*)lo)[i * 2 + 1] = ll1;
    }
}

// ---------------------------------------------------------------------------
// Pitched split: src [rows, cols] row-major -> dst rows with pitch elems.
// cols % 4 == 0, pitch % 4 == 0.  hi/lo already offset to the column base.
// ---------------------------------------------------------------------------
__global__ void split_pitch_kernel(const float* __restrict__ src,
                                   __nv_bfloat16* __restrict__ hi,
                                   __nv_bfloat16* __restrict__ lo,
                                   int cols, int pitch, size_t n4)
{
    size_t i = (size_t)blockIdx.x * blockDim.x + threadIdx.x;
    size_t stride = (size_t)gridDim.x * blockDim.x;
    for (; i < n4; i += stride) {
        size_t e = i * 4;
        int k = (int)(e / cols), n = (int)(e % cols);
        float4 v = ((const float4*)src)[i];
        size_t d = (size_t)k * pitch + n;
        __nv_bfloat16 h0 = __float2bfloat16(v.x);
        __nv_bfloat16 h1 = __float2bfloat16(v.y);
        __nv_bfloat16 h2 = __float2bfloat16(v.z);
        __nv_bfloat16 h3 = __float2bfloat16(v.w);
        __nv_bfloat162 hh0 = {h0, h1}, hh1 = {h2, h3};
        __nv_bfloat162 ll0 = {__float2bfloat16(v.x - __bfloat162float(h0)),
                              __float2bfloat16(v.y - __bfloat162float(h1))};
        __nv_bfloat162 ll1 = {__float2bfloat16(v.z - __bfloat162float(h2)),
                              __float2bfloat16(v.w - __bfloat162float(h3))};
        *(__nv_bfloat162*)(hi + d)     = hh0;
        *(__nv_bfloat162*)(hi + d + 2) = hh1;
        *(__nv_bfloat162*)(lo + d)     = ll0;
        *(__nv_bfloat162*)(lo + d + 2) = ll1;
    }
}

__global__ void concat_bias_kernel(const float* __restrict__ bz,
                                   const float* __restrict__ br,
                                   const float* __restrict__ bh,
                                   float* __restrict__ outb)
{
    int i = blockIdx.x * blockDim.x + threadIdx.x;
    if (i < 512)       outb[i] = bz[i];
    else if (i < 1024) outb[i] = br[i - 512];
    else if (i < NG)   outb[i] = bh[i - 1024];
}

// ---------------------------------------------------------------------------
// MMA helpers
// ---------------------------------------------------------------------------
__device__ __forceinline__ uint32_t smem_addr_u32(const void* p) {
    uint32_t a;
    asm("{ .reg .u64 t; cvta.to.shared.u64 t, %1; cvt.u32.u64 %0, t; }"
        : "=r"(a) : "l"(p));
    return a;
}
__device__ __forceinline__ void ldsm_x4(uint32_t& r0, uint32_t& r1,
                                        uint32_t& r2, uint32_t& r3, uint32_t a) {
    asm volatile("ldmatrix.sync.aligned.m8n8.x4.shared.b16 {%0,%1,%2,%3}, [%4];"
                 : "=r"(r0), "=r"(r1), "=r"(r2), "=r"(r3) : "r"(a));
}
__device__ __forceinline__ void ldsm_x4_t(uint32_t& r0, uint32_t& r1,
                                          uint32_t& r2, uint32_t& r3, uint32_t a) {
    asm volatile("ldmatrix.sync.aligned.m8n8.x4.trans.shared.b16 {%0,%1,%2,%3}, [%4];"
                 : "=r"(r0), "=r"(r1), "=r"(r2), "=r"(r3) : "r"(a));
}
__device__ __forceinline__ void mma_bf16(float* d, const uint32_t* a,
                                         uint32_t b0, uint32_t b1) {
    asm volatile(
        "mma.sync.aligned.m16n8k16.row.col.f32.bf16.bf16.f32 "
        "{%0,%1,%2,%3}, {%4,%5,%6,%7}, {%8,%9}, {%0,%1,%2,%3};"
        : "+f"(d[0]), "+f"(d[1]), "+f"(d[2]), "+f"(d[3])
        : "r"(a[0]), "r"(a[1]), "r"(a[2]), "r"(a[3]), "r"(b0), "r"(b1));
}

#define APITCH 40
#define BPITCH 136
#define SM_AHI 0
#define SM_ALO 20480
#define SM_BHI 40960
#define SM_BLO 58368
#define QKV_SMEM 75776

// ---------------------------------------------------------------------------
// Generalized batched bf16x3 GEMM (EXACT R15 version — fp32 C only).
//   mode2: Kend = min(rowBase+128, K) for lower-triangular A (PV).
// ---------------------------------------------------------------------------
__global__ void __launch_bounds__(256) mma_gemm_gen(
    const __nv_bfloat16* __restrict__ Ah, const __nv_bfloat16* __restrict__ Al,
    const __nv_bfloat16* __restrict__ Bh, const __nv_bfloat16* __restrict__ Bl,
    const float* __restrict__ bias, float* __restrict__ C,
    int N, int K,
    size_t aStride, size_t bStride, size_t cStride, int mode2)
{
    extern __shared__ char smem[];
    int tid = threadIdx.x, lane = tid & 31, warp = tid >> 5;
    int bz = blockIdx.z;
    int rowBase = blockIdx.y * 128, colBase = blockIdx.x * 128;
    int Kend = K;
    if (mode2) Kend = (rowBase + 128 < K) ? rowBase + 128 : K;
    int warp_m = (warp >> 1) * 32, warp_n = (warp & 1) * 64;

    Ah += aStride * (size_t)bz;  Al += aStride * (size_t)bz;
    Bh += bStride * (size_t)bz;  Bl += bStride * (size_t)bz;
    C  += cStride * (size_t)bz;

    uint32_t sA = smem_addr_u32(smem);
    uint32_t sAhi = sA + SM_AHI, sAlo = sA + SM_ALO;
    uint32_t sBhi = sA + SM_BHI, sBlo = sA + SM_BLO;

    int q = lane >> 3, r = lane & 7;
    int a_row[2];
    a_row[0] = warp_m + (q & 1) * 8 + r;
    a_row[1] = a_row[0] + 16;
    int a_col = (q >> 1) * 8;
    int b_k = (q & 1) * 8 + r;
    int b_n[4];
#pragma unroll
    for (int p = 0; p < 4; p++) b_n[p] = warp_n + p * 16 + (q >> 1) * 8;

    int a_ch0 = tid, a_ch1 = tid + 256;
    int ar0 = a_ch0 >> 2, as0 = a_ch0 & 3, ar1 = a_ch1 >> 2, as1 = a_ch1 & 3;
    int bk0 = a_ch0 >> 4, bs0 = a_ch0 & 15, bk1 = a_ch1 >> 4, bs1 = a_ch1 & 15;

    const __nv_bfloat16* Ahp0 = Ah + (size_t)(rowBase + ar0) * K + as0 * 8;
    const __nv_bfloat16* Ahp1 = Ah + (size_t)(rowBase + ar1) * K + as1 * 8;
    const __nv_bfloat16* Alp0 = Al + (size_t)(rowBase + ar0) * K + as0 * 8;
    const __nv_bfloat16* Alp1 = Al + (size_t)(rowBase + ar1) * K + as1 * 8;
    const __nv_bfloat16* Bhp0 = Bh + (size_t)bk0 * N + colBase + bs0 * 8;
    const __nv_bfloat16* Bhp1 = Bh + (size_t)bk1 * N + colBase + bs1 * 8;
    const __nv_bfloat16* Blp0 = Bl + (size_t)bk0 * N + colBase + bs0 * 8;
    const __nv_bfloat16* Blp1 = Bl + (size_t)bk1 * N + colBase + bs1 * 8;

    float acc[2][8][4];
#pragma unroll
    for (int i = 0; i < 2; i++)
#pragma unroll
        for (int j = 0; j < 8; j++)
#pragma unroll
            for (int v = 0; v < 4; v++) acc[i][j][v] = 0.0f;

    uint4 pah0, pah1, pal0, pal1, pbh0, pbh1, pbl0, pbl1;
    pah0 = *(const uint4*)(Ahp0); pah1 = *(const uint4*)(Ahp1);
    pal0 = *(const uint4*)(Alp0); pal1 = *(const uint4*)(Alp1);
    pbh0 = *(const uint4*)(Bhp0); pbh1 = *(const uint4*)(Bhp1);
    pbl0 = *(const uint4*)(Blp0); pbl1 = *(const uint4*)(Blp1);
    {
        char* base = (char*)smem;
        *(uint4*)(base + SM_AHI + (ar0 * APITCH + as0 * 8) * 2) = pah0;
        *(uint4*)(base + SM_AHI + (ar1 * APITCH + as1 * 8) * 2) = pah1;
        *(uint4*)(base + SM_ALO + (ar0 * APITCH + as0 * 8) * 2) = pal0;
        *(uint4*)(base + SM_ALO + (ar1 * APITCH + as1 * 8) * 2) = pal1;
        *(uint4*)(base + SM_BHI + (bk0 * BPITCH + bs0 * 8) * 2) = pbh0;
        *(uint4*)(base + SM_BHI + (bk1 * BPITCH + bs1 * 8) * 2) = pbh1;
        *(uint4*)(base + SM_BLO + (bk0 * BPITCH + bs0 * 8) * 2) = pbl0;
        *(uint4*)(base + SM_BLO + (bk1 * BPITCH + bs1 * 8) * 2) = pbl1;
    }
    __syncthreads();

    const int nTiles = Kend / 32;
    int buf = 0;
    for (int kt = 0; kt < nTiles; kt++) {
        bool nxt = (kt + 1 < nTiles);
        if (nxt) {
            int ko = (kt + 1) * 32;
            pah0 = *(const uint4*)(Ahp0 + ko); pah1 = *(const uint4*)(Ahp1 + ko);
            pal0 = *(const uint4*)(Alp0 + ko); pal1 = *(const uint4*)(Alp1 + ko);
            pbh0 = *(const uint4*)(Bhp0 + (size_t)ko * N);
            pbh1 = *(const uint4*)(Bhp1 + (size_t)ko * N);
            pbl0 = *(const uint4*)(Blp0 + (size_t)ko * N);
            pbl1 = *(const uint4*)(Blp1 + (size_t)ko * N);
        }

#pragma unroll
        for (int ks = 0; ks < 2; ks++) {
            uint32_t aoffh = sAhi + ((buf * 128) * APITCH + ks * 16 + a_col) * 2;
            uint32_t aoffl = sAlo + ((buf * 128) * APITCH + ks * 16 + a_col) * 2;
            uint32_t ahi[2][4], alo[2][4];
#pragma unroll
            for (int i = 0; i < 2; i++) {
                ldsm_x4(ahi[i][0], ahi[i][1], ahi[i][2], ahi[i][3],
                        aoffh + a_row[i] * (APITCH * 2));
                ldsm_x4(alo[i][0], alo[i][1], alo[i][2], alo[i][3],
                        aoffl + a_row[i] * (APITCH * 2));
            }
            uint32_t bhi[4][4], blo[4][4];
            uint32_t bkrow = (buf * 32 + ks * 16 + b_k) * (BPITCH * 2);
#pragma unroll
            for (int p = 0; p < 4; p++) {
                ldsm_x4_t(bhi[p][0], bhi[p][1], bhi[p][2], bhi[p][3],
                          sBhi + bkrow + b_n[p] * 2);
                ldsm_x4_t(blo[p][0], blo[p][1], blo[p][2], blo[p][3],
                          sBlo + bkrow + b_n[p] * 2);
            }
#pragma unroll
            for (int i = 0; i < 2; i++) {
#pragma unroll
                for (int p = 0; p < 4; p++) {
#pragma unroll
                    for (int t = 0; t < 2; t++) {
                        int j = p * 2 + t;
                        uint32_t b0h = bhi[p][t * 2], b1h = bhi[p][t * 2 + 1];
                        uint32_t b0l = blo[p][t * 2], b1l = blo[p][t * 2 + 1];
                        mma_bf16(acc[i][j], ahi[i], b0h, b1h);
                        mma_bf16(acc[i][j], ahi[i], b0l, b1l);
                        mma_bf16(acc[i][j], alo[i], b0h, b1h);
                    }
                }
            }
        }

        if (nxt) {
            int nb = buf ^ 1;
            char* base = (char*)smem;
            *(uint4*)(base + SM_AHI + ((nb * 128 + ar0) * APITCH + as0 * 8) * 2) = pah0;
            *(uint4*)(base + SM_AHI + ((nb * 128 + ar1) * APITCH + as1 * 8) * 2) = pah1;
            *(uint4*)(base + SM_ALO + ((nb * 128 + ar0) * APITCH + as0 * 8) * 2) = pal0;
            *(uint4*)(base + SM_ALO + ((nb * 128 + ar1) * APITCH + as1 * 8) * 2) = pal1;
            *(uint4*)(base + SM_BHI + ((nb * 32 + bk0) * BPITCH + bs0 * 8) * 2) = pbh0;
            *(uint4*)(base + SM_BHI + ((nb * 32 + bk1) * BPITCH + bs1 * 8) * 2) = pbh1;
            *(uint4*)(base + SM_BLO + ((nb * 32 + bk0) * BPITCH + bs0 * 8) * 2) = pbl0;
            *(uint4*)(base + SM_BLO + ((nb * 32 + bk1) * BPITCH + bs1 * 8) * 2) = pbl1;
        }
        __syncthreads();
        buf ^= 1;
    }

    int g = lane >> 2, tig = lane & 3;
#pragma unroll
    for (int i = 0; i < 2; i++) {
#pragma unroll
        for (int j = 0; j < 8; j++) {
            int col = colBase + warp_n + j * 8 + tig * 2;
            float2 bv = make_float2(0.f, 0.f);
            if (bias) bv = *(const float2*)(bias + col);
            int r0 = rowBase + warp_m + i * 16 + g;
            float2 o0 = make_float2(acc[i][j][0] + bv.x, acc[i][j][1] + bv.y);
            float2 o1 = make_float2(acc[i][j][2] + bv.x, acc[i][j][3] + bv.y);
            *(float2*)(C + (size_t)r0 * N + col) = o0;
            *(float2*)(C + (size_t)(r0 + 8) * N + col) = o1;
        }
    }
}

// ---------------------------------------------------------------------------
// Tensor-core scores GEMM (unchanged).
// ---------------------------------------------------------------------------
#define SC_APITCH 40
#define SC_AHI 0
#define SC_ALO 20480
#define SC_BHI 40960
#define SC_BLO 61440
#define SC_SMEM 81920

__global__ void __launch_bounds__(256) scores_mma_kernel(
    const __nv_bfloat16* __restrict__ Qh, const __nv_bfloat16* __restrict__ Ql,
    const __nv_bfloat16* __restrict__ Kh, const __nv_bfloat16* __restrict__ Kl,
    float* __restrict__ S)
{
    extern __shared__ char smem[];
    const int KD = DPROJ;
    int tid = threadIdx.x, lane = tid & 31, warp = tid >> 5;
    int bz = blockIdx.z;
    int rowBase = blockIdx.y * 128, colBase = blockIdx.x * 128;
    if (rowBase + 127 < colBase) return;
    int warp_m = (warp >> 1) * 32, warp_n = (warp & 1) * 64;

    uint32_t sA = smem_addr_u32(smem);
    uint32_t sAhi = sA + SC_AHI, sAlo = sA + SC_ALO;
    uint32_t sBhi = sA + SC_BHI, sBlo = sA + SC_BLO;

    int q = lane >> 3, r = lane & 7;
    int a_row[2];
    a_row[0] = warp_m + (q & 1) * 8 + r;
    a_row[1] = a_row[0] + 16;
    int a_col = (q >> 1) * 8;
    int b_row[4];
#pragma unroll
    for (int p = 0; p < 4; p++) b_row[p] = warp_n + p * 16 + (q & 1) * 8 + r;

    int ch0 = tid, ch1 = tid + 256;
    int ar0 = ch0 >> 2, as0 = ch0 & 3, ar1 = ch1 >> 2, as1 = ch1 & 3;

    size_t bbase = (size_t)bz * SEQ;
    const __nv_bfloat16* Ahp0 = Qh + (bbase + rowBase + ar0) * KD + as0 * 8;
    const __nv_bfloat16* Ahp1 = Qh + (bbase + rowBase + ar1) * KD + as1 * 8;
    const __nv_bfloat16* Alp0 = Ql + (bbase + rowBase + ar0) * KD + as0 * 8;
    const __nv_bfloat16* Alp1 = Ql + (bbase + rowBase + ar1) * KD + as1 * 8;
    const __nv_bfloat16* Bhp0 = Kh + (bbase + colBase + ar0) * KD + as0 * 8;
    const __nv_bfloat16* Bhp1 = Kh + (bbase + colBase + ar1) * KD + as1 * 8;
    const __nv_bfloat16* Blp0 = Kl + (bbase + colBase + ar0) * KD + as0 * 8;
    const __nv_bfloat16* Blp1 = Kl + (bbase + colBase + ar1) * KD + as1 * 8;

    float acc[2][8][4];
#pragma unroll
    for (int i = 0; i < 2; i++)
#pragma unroll
        for (int j = 0; j < 8; j++)
#pragma unroll
            for (int v = 0; v < 4; v++) acc[i][j][v] = 0.0f;

    uint4 pah0, pah1, pal0, pal1, pbh0, pbh1, pbl0, pbl1;
    pah0 = *(const uint4*)(Ahp0); pah1 = *(const uint4*)(Ahp1);
    pal0 = *(const uint4*)(Alp0); pal1 = *(const uint4*)(Alp1);
    pbh0 = *(const uint4*)(Bhp0); pbh1 = *(const uint4*)(Bhp1);
    pbl0 = *(const uint4*)(Blp0); pbl1 = *(const uint4*)(Blp1);
    {
        char* base = (char*)smem;
        *(uint4*)(base + SC_AHI + (ar0 * SC_APITCH + as0 * 8) * 2) = pah0;
        *(uint4*)(base + SC_AHI + (ar1 * SC_APITCH + as1 * 8) * 2) = pah1;
        *(uint4*)(base + SC_ALO + (ar0 * SC_APITCH + as0 * 8) * 2) = pal0;
        *(uint4*)(base + SC_ALO + (ar1 * SC_APITCH + as1 * 8) * 2) = pal1;
        *(uint4*)(base + SC_BHI + (ar0 * SC_APITCH + as0 * 8) * 2) = pbh0;
        *(uint4*)(base + SC_BHI + (ar1 * SC_APITCH + as1 * 8) * 2) = pbh1;
        *(uint4*)(base + SC_BLO + (ar0 * SC_APITCH + as0 * 8) * 2) = pbl0;
        *(uint4*)(base + SC_BLO + (ar1 * SC_APITCH + as1 * 8) * 2) = pbl1;
    }
    __syncthreads();

    const int nTiles = KD / 32;
    int buf = 0;
    for (int kt = 0; kt < nTiles; kt++) {
        bool nxt = (kt + 1 < nTiles);
        if (nxt) {
            int ko = (kt + 1) * 32;
            pah0 = *(const uint4*)(Ahp0 + ko); pah1 = *(const uint4*)(Ahp1 + ko);
            pal0 = *(const uint4*)(Alp0 + ko); pal1 = *(const uint4*)(Alp1 + ko);
            pbh0 = *(const uint4*)(Bhp0 + ko); pbh1 = *(const uint4*)(Bhp1 + ko);
            pbl0 = *(const uint4*)(Blp0 + ko); pbl1 = *(const uint4*)(Blp1 + ko);
        }

#pragma unroll
        for (int ks = 0; ks < 2; ks++) {
            uint32_t aoffh = sAhi + ((buf * 128) * SC_APITCH + ks * 16 + a_col) * 2;
            uint32_t aoffl = sAlo + ((buf * 128) * SC_APITCH + ks * 16 + a_col) * 2;
            uint32_t ahi[2][4], alo[2][4];
#pragma unroll
            for (int i = 0; i < 2; i++) {
                ldsm_x4(ahi[i][0], ahi[i][1], ahi[i][2], ahi[i][3],
                        aoffh + a_row[i] * (SC_APITCH * 2));
                ldsm_x4(alo[i][0], alo[i][1], alo[i][2], alo[i][3],
                        aoffl + a_row[i] * (SC_APITCH * 2));
            }
            uint32_t boffh = sBhi + ((buf * 128) * SC_APITCH + ks * 16 + a_col) * 2;
            uint32_t boffl = sBlo + ((buf * 128) * SC_APITCH + ks * 16 + a_col) * 2;
            uint32_t bhi[4][4], blo[4][4];
#pragma unroll
            for (int p = 0; p < 4; p++) {
                ldsm_x4(bhi[p][0], bhi[p][1], bhi[p][2], bhi[p][3],
                        boffh + b_row[p] * (SC_APITCH * 2));
                ldsm_x4(blo[p][0], blo[p][1], blo[p][2], blo[p][3],
                        boffl + b_row[p] * (SC_APITCH * 2));
            }
#pragma unroll
            for (int i = 0; i < 2; i++) {
#pragma unroll
                for (int p = 0; p < 4; p++) {
#pragma unroll
                    for (int t = 0; t < 2; t++) {
                        int j = p * 2 + t;
                        uint32_t b0h = bhi[p][t], b1h = bhi[p][t + 2];
                        uint32_t b0l = blo[p][t], b1l = blo[p][t + 2];
                        mma_bf16(acc[i][j], ahi[i], b0h, b1h);
                        mma_bf16(acc[i][j], ahi[i], b0l, b1l);
                        mma_bf16(acc[i][j], alo[i], b0h, b1h);
                    }
                }
            }
        }

        if (nxt) {
            int nb = buf ^ 1;
            char* base = (char*)smem;
            *(uint4*)(base + SC_AHI + ((nb * 128 + ar0) * SC_APITCH + as0 * 8) * 2) = pah0;
            *(uint4*)(base + SC_AHI + ((nb * 128 + ar1) * SC_APITCH + as1 * 8) * 2) = pah1;
            *(uint4*)(base + SC_ALO + ((nb * 128 + ar0) * SC_APITCH + as0 * 8) * 2) = pal0;
            *(uint4*)(base + SC_ALO + ((nb * 128 + ar1) * SC_APITCH + as1 * 8) * 2) = pal1;
            *(uint4*)(base + SC_BHI + ((nb * 128 + ar0) * SC_APITCH + as0 * 8) * 2) = pbh0;
            *(uint4*)(base + SC_BHI + ((nb * 128 + ar1) * SC_APITCH + as1 * 8) * 2) = pbh1;
            *(uint4*)(base + SC_BLO + ((nb * 128 + ar0) * SC_APITCH + as0 * 8) * 2) = pbl0;
            *(uint4*)(base + SC_BLO + ((nb * 128 + ar1) * SC_APITCH + as1 * 8) * 2) = pbl1;
        }
        __syncthreads();
        buf ^= 1;
    }

    float* Sb = S + (size_t)bz * SEQ * SEQ;
    int g = lane >> 2, tig = lane & 3;
#pragma unroll
    for (int i = 0; i < 2; i++) {
#pragma unroll
        for (int j = 0; j < 8; j++) {
            int col = colBase + warp_n + j * 8 + tig * 2;
            int r0 = rowBase + warp_m + i * 16 + g;
            *(float2*)(Sb + (size_t)r0 * SEQ + col) =
                make_float2(acc[i][j][0], acc[i][j][1]);
            *(float2*)(Sb + (size_t)(r0 + 8) * SEQ + col) =
                make_float2(acc[i][j][2], acc[i][j][3]);
        }
    }
}

// ---------------------------------------------------------------------------
// Causal row softmax: fp32 scores -> bf16 (hi, lo) probabilities.
// ---------------------------------------------------------------------------
__global__ void softmax_causal_kernel()
{
    int r = blockIdx.x, b = blockIdx.y;
    size_t rowoff = ((size_t)b * SEQ + r) * SEQ;
    const float* row = g_S + rowoff;
    int len = r + 1;
    int tid = threadIdx.x;
    __shared__ float buf[SEQ];
    __shared__ float red[256];
    const float inv = rsqrtf(512.0f);

    float m = -3.4e38f;
    for (int i = tid; i < len; i += 256) m = fmaxf(m, row[i]);
    red[tid] = m; __syncthreads();
    for (int s = 128; s; s >>= 1) { if (tid < s) red[tid] = fmaxf(red[tid], red[tid + s]); __syncthreads(); }
    m = red[0] * inv;
    __syncthreads();

    float ssum = 0.0f;
    for (int i = tid; i < len; i += 256) {
        float e = __expf(row[i] * inv - m);
        buf[i] = e;
        ssum += e;
    }
    red[tid] = ssum; __syncthreads();
    for (int s = 128; s; s >>= 1) { if (tid < s) red[tid] += red[tid + s]; __syncthreads(); }
    float denom = 1.0f / red[0];
    __syncthreads();

    for (int i = tid; i < SEQ; i += 256) {
        float v = (i < len) ? buf[i] * denom : 0.0f;
        __nv_bfloat16 hi = __float2bfloat16(v);
        __nv_bfloat16 lo = __float2bfloat16(v - __bfloat162float(hi));
        g_Phi[rowoff + i] = hi;
        g_Plo[rowoff + i] = lo;
    }
}

// ---------------------------------------------------------------------------
// Prefix pooling + h0.
// ---------------------------------------------------------------------------
__global__ void pool_kernel(const float* __restrict__ Wscore,
                            const float* __restrict__ Wp2h,
                            const float* __restrict__ bp2h)
{
    int b = blockIdx.x;
    const float* feat = g_feat + (size_t)b * SEQ * DPROJ;
    __shared__ float wsc[512];
    __shared__ float sc[512];
    __shared__ float pooled[512];
    __shared__ float red[256];
    int tid = threadIdx.x;

    for (int i = tid; i < 512; i += 256) wsc[i] = Wscore[i];
    __syncthreads();

    int w = tid >> 5, l = tid & 31;
    for (int u = w; u < ASSIST; u += 8) {
        float s = 0.0f;
        for (int p = l; p < DPROJ; p += 32)
            s = fmaf(feat[(size_t)u * DPROJ + p], wsc[p], s);
#pragma unroll
        for (int o = 16; o; o >>= 1) s += __shfl_xor_sync(0xffffffffu, s, o);
        if (l == 0) sc[u] = s;
    }
    __syncthreads();

    float m = fmaxf(sc[tid], sc[tid + 256]);
    red[tid] = m; __syncthreads();
    for (int s = 128; s; s >>= 1) { if (tid < s) red[tid] = fmaxf(red[tid], red[tid + s]); __syncthreads(); }
    m = red[0]; __syncthreads();

    float e0 = expf(sc[tid] - m), e1 = expf(sc[tid + 256] - m);
    red[tid] = e0 + e1; __syncthreads();
    for (int s = 128; s; s >>= 1) { if (tid < s) red[tid] += red[tid + s]; __syncthreads(); }
    float inv = 1.0f / red[0];
    __syncthreads();
    sc[tid] = e0 * inv; sc[tid + 256] = e1 * inv;
    __syncthreads();

    for (int p = tid; p < DPROJ; p += 256) {
        float acc = 0.0f;
        for (int u = 0; u < ASSIST; u++)
            acc = fmaf(sc[u], feat[(size_t)u * DPROJ + p], acc);
        pooled[p] = acc;
    }
    __syncthreads();

    for (int c = tid; c < DMEM; c += 256) {
        float acc = bp2h[c];
        for (int k = 0; k < DPROJ; k++)
            acc = fmaf(pooled[k], Wp2h[(size_t)k * DMEM + c], acc);
        g_h[b * DMEM + c] = tanhf(acc);
    }
}

__global__ void init_out_kernel(float* __restrict__ out, const float* __restrict__ bmem)
{
    int i = blockIdx.x * blockDim.x + threadIdx.x;
    if (i < BATCH * RUN) out[i] = bmem[0];
}

// ---------------------------------------------------------------------------
// Cluster-based sequential scan — R11 structure; G inputs now combined
// [RUN, 1536] rows (z | r | h sections).
// ---------------------------------------------------------------------------
#define SCAN_THREADS 512
#define CL 16

#define H_OFF    0
#define RH_OFF   2048
#define PART_OFF 4096
#define WM_OFF   8192
#define SCAN_SMEM 8320

__device__ __forceinline__ uint32_t mapa_rank(uint32_t saddr, uint32_t rank) {
    uint32_t r;
    asm("mapa.shared::cluster.u32 %0, %1, %2;" : "=r"(r) : "r"(saddr), "r"(rank));
    return r;
}
__device__ __forceinline__ void stc_f32(uint32_t addr, float v) {
    asm volatile("st.shared::cluster.f32 [%0], %1;" :: "r"(addr), "f"(v));
}
#define CLUSTER_SYNC() do { \
    asm volatile("barrier.cluster.arrive.aligned;" ::: "memory"); \
    asm volatile("barrier.cluster.wait.aligned;" ::: "memory"); \
} while (0)

__global__ void __launch_bounds__(SCAN_THREADS, 1) scan_cluster(
    const float* __restrict__ Uz, const float* __restrict__ Ur,
    const float* __restrict__ Uh, const float* __restrict__ Wmem,
    const float* __restrict__ G, float* __restrict__ out)
{
    extern __shared__ char smem[];
    float*  h_s  = (float*)(smem + H_OFF);
    float*  rh_s = (float*)(smem + RH_OFF);
    float2* part = (float2*)(smem + PART_OFF);
    float*  wm_s = (float*)(smem + WM_OFF);

    int tid = threadIdx.x;
    int c   = tid & 31;
    int seg = tid >> 5;
    int kbase = seg * 32;

    uint32_t rank;
    asm("mov.u32 %0, %%cluster_ctarank;" : "=r"(rank));
    int cg0 = (int)rank * 32;
    int gb  = blockIdx.x >> 4;

    float uz[32], ur[32], uh[32];
#pragma unroll
    for (int i = 0; i < 32; i++) {
        uz[i] = Uz[(size_t)(kbase + i) * DMEM + cg0 + c];
        ur[i] = Ur[(size_t)(kbase + i) * DMEM + cg0 + c];
        uh[i] = Uh[(size_t)(kbase + i) * DMEM + cg0 + c];
    }
    if (tid < 32) wm_s[tid] = Wmem[cg0 + tid];

    h_s[tid] = __ldcg(&g_h[(size_t)gb * DMEM + tid]);
    __syncthreads();

    uint32_t rh_base = smem_addr_u32(rh_s);
    uint32_t h_base  = smem_addr_u32(h_s);

    const float dtc = 1.0f / 1535.0f;
    float zreg = 0.0f;

    for (int t = 0; t < RUN; t++) {
        float dtv = (t == 0) ? 0.0f : dtc;

        float gA = 0.0f, gH = 0.0f;
        size_t grow = ((size_t)(gb * RUN + t)) * NG;
        if (tid < 64) {
            int cc = tid & 31, mat = tid >> 5;       // 0 = z, 1 = r
            gA = __ldg(&G[grow + mat * 512 + cg0 + cc]);
        }
        if (tid < 32) {
            gH = __ldg(&G[grow + 1024 + cg0 + tid]);
        }

        float pz = 0.f, pr = 0.f;
        const float4* hp = (const float4*)&h_s[kbase];
#pragma unroll
        for (int i = 0; i < 8; i++) {
            float4 h4 = hp[i];
            pz = fmaf(h4.x, uz[4*i+0], pz); pr = fmaf(h4.x, ur[4*i+0], pr);
            pz = fmaf(h4.y, uz[4*i+1], pz); pr = fmaf(h4.y, ur[4*i+1], pr);
            pz = fmaf(h4.z, uz[4*i+2], pz); pr = fmaf(h4.z, ur[4*i+2], pr);
            pz = fmaf(h4.w, uz[4*i+3], pz); pr = fmaf(h4.w, ur[4*i+3], pr);
        }
        part[tid] = make_float2(pz, pr);
        __syncthreads();

        if (tid < 64) {
            int cc = tid & 31, mat = tid >> 5;
            float s = 0.0f;
#pragma unroll
            for (int sg = 0; sg < 16; sg++) {
                float2 p = part[sg * 32 + cc];
                s += mat ? p.y : p.x;
            }
            float v = gA + s;
            float sig = 1.0f / (1.0f + __expf(-v));
            if (mat == 0) {
                zreg = sig;
            } else {
                float rhv = sig * h_s[cg0 + cc];
                uint32_t a = rh_base + (uint32_t)(cg0 + cc) * 4u;
#pragma unroll
                for (int rk = 0; rk < CL; rk++)
                    stc_f32(mapa_rank(a, (uint32_t)rk), rhv);
            }
        }
        CLUSTER_SYNC();

        float ph = 0.f;
        const float4* rp = (const float4*)&rh_s[kbase];
#pragma unroll
        for (int i = 0; i < 8; i++) {
            float4 r4 = rp[i];
            ph = fmaf(r4.x, uh[4*i+0], ph);
            ph = fmaf(r4.y, uh[4*i+1], ph);
            ph = fmaf(r4.z, uh[4*i+2], ph);
            ph = fmaf(r4.w, uh[4*i+3], ph);
        }
        part[tid].x = ph;
        __syncthreads();

        if (tid < 32) {
            int cc = tid;
            float s = 0.0f;
#pragma unroll
            for (int sg = 0; sg < 16; sg++)
                s += part[sg * 32 + cc].x;
            float hh   = tanhf(gH + s);
            int   cg   = cg0 + cc;
            float hold = h_s[cg];
            float hnew = hold + zreg * (hh - hold);
            float hout = hnew + dtv * (hnew - hold);
            if (t < RUN - 1) {
                uint32_t a = h_base + (uint32_t)cg * 4u;
#pragma unroll
                for (int rk = 0; rk < CL; rk++)
                    stc_f32(mapa_rank(a, (uint32_t)rk), hout);
            }
            float lv = hout * wm_s[cc];
#pragma unroll
            for (int o = 16; o; o >>= 1)
                lv += __shfl_xor_sync(0xffffffffu, lv, o);
            if (cc == 0)
                atomicAdd(&out[gb * RUN + t], lv);
        }
        CLUSTER_SYNC();
    }
}

// ---------------------------------------------------------------------------
// Host
// ---------------------------------------------------------------------------
extern "C" void kernel_launch(void* const* d_in, const int* in_sizes, int n_in,
                              void* d_out, int out_size)
{
    const float* x      = (const float*)d_in[0];
    const float* Wq     = (const float*)d_in[1];
    const float* bq     = (const float*)d_in[2];
    const float* Wk     = (const float*)d_in[3];
    const float* bk     = (const float*)d_in[4];
    const float* Wv     = (const float*)d_in[5];
    const float* bv     = (const float*)d_in[6];
    const float* Wz     = (const float*)d_in[7];
    const float* Uz     = (const float*)d_in[8];
    const float* bz     = (const float*)d_in[9];
    const float* Wr     = (const float*)d_in[10];
    const float* Ur     = (const float*)d_in[11];
    const float* br     = (const float*)d_in[12];
    const float* Wh     = (const float*)d_in[13];
    const float* Uh     = (const float*)d_in[14];
    const float* bh     = (const float*)d_in[15];
    const float* Wmem   = (const float*)d_in[16];
    const float* bmem   = (const float*)d_in[17];
    const float* Wp2h   = (const float*)d_in[18];
    const float* bp2h   = (const float*)d_in[19];
    const float* Wscore = (const float*)d_in[20];
    (void)in_sizes; (void)n_in;
    float* out = (float*)d_out;

    float *pQ, *pK, *pV, *pS, *pF, *pG, *pbzrh;
    cudaGetSymbolAddress((void**)&pQ,  g_Q);
    cudaGetSymbolAddress((void**)&pK,  g_K);
    cudaGetSymbolAddress((void**)&pV,  g_V);
    cudaGetSymbolAddress((void**)&pS,  g_S);
    cudaGetSymbolAddress((void**)&pF,  g_feat);
    cudaGetSymbolAddress((void**)&pG,  g_G);
    cudaGetSymbolAddress((void**)&pbzrh, g_bzrh);

    __nv_bfloat16 *pxh, *pxl, *pWh, *pWl, *pPhi, *pPlo, *pVh, *pVl,
                  *pfah, *pfal, *pUwCh, *pUwCl;
    cudaGetSymbolAddress((void**)&pxh,  g_xhi);
    cudaGetSymbolAddress((void**)&pxl,  g_xlo);
    cudaGetSymbolAddress((void**)&pWh,  g_Whi);
    cudaGetSymbolAddress((void**)&pWl,  g_Wlo);
    cudaGetSymbolAddress((void**)&pPhi, g_Phi);
    cudaGetSymbolAddress((void**)&pPlo, g_Plo);
    cudaGetSymbolAddress((void**)&pVh,  g_Vh);
    cudaGetSymbolAddress((void**)&pVl,  g_Vl);
    cudaGetSymbolAddress((void**)&pfah, g_fah);
    cudaGetSymbolAddress((void**)&pfal, g_fal);
    cudaGetSymbolAddress((void**)&pUwCh, g_UwCh);
    cudaGetSymbolAddress((void**)&pUwCl, g_UwCl);

    dim3 t256(256);
    const size_t WSZ  = (size_t)DIN * DPROJ;
    const size_t QKSZ = (size_t)ROWS * DPROJ;   // 4M
    const size_t UWSZ = (size_t)DPROJ * DMEM;   // 256K

    cudaFuncSetAttribute(mma_gemm_gen,
                         cudaFuncAttributeMaxDynamicSharedMemorySize, QKV_SMEM);
    cudaFuncSetAttribute(scores_mma_kernel,
                         cudaFuncAttributeMaxDynamicSharedMemorySize, SC_SMEM);

    // split x and W into bf16 (hi, lo)
    split_kernel<<<2048, t256>>>(x,  pxh, pxl, (size_t)ROWS * DIN / 4);
    split_kernel<<<512,  t256>>>(Wq, pWh,           pWl,           WSZ / 4);
    split_kernel<<<512,  t256>>>(Wk, pWh + WSZ,     pWl + WSZ,     WSZ / 4);
    split_kernel<<<512,  t256>>>(Wv, pWh + 2 * WSZ, pWl + 2 * WSZ, WSZ / 4);

    // QKV projections (tensor cores) -> fp32
    {
        dim3 g(DPROJ / 128, ROWS / 128, 1);
        mma_gemm_gen<<<g, t256, QKV_SMEM>>>(pxh, pxl, pWh,           pWl,           bq, pQ, DPROJ, DIN, 0, 0, 0, 0);
        mma_gemm_gen<<<g, t256, QKV_SMEM>>>(pxh, pxl, pWh + WSZ,     pWl + WSZ,     bk, pK, DPROJ, DIN, 0, 0, 0, 0);
        mma_gemm_gen<<<g, t256, QKV_SMEM>>>(pxh, pxl, pWh + 2 * WSZ, pWl + 2 * WSZ, bv, pV, DPROJ, DIN, 0, 0, 0, 0);
    }

    // split Q, K (reuse g_xhi region), V (own buffers)
    __nv_bfloat16* pQh = pxh;
    __nv_bfloat16* pQl = pxh + QKSZ;
    __nv_bfloat16* pKh = pxh + 2 * QKSZ;
    __nv_bfloat16* pKl = pxh + 3 * QKSZ;
    split_kernel<<<1024, t256>>>(pQ, pQh, pQl, QKSZ / 4);
    split_kernel<<<1024, t256>>>(pK, pKh, pKl, QKSZ / 4);
    split_kernel<<<1024, t256>>>(pV, pVh, pVl, QKSZ / 4);

    // scores = Q K^T (tensor cores, causal tile skip)
    {
        dim3 g(SEQ / 128, SEQ / 128, BATCH);
        scores_mma_kernel<<<g, t256, SC_SMEM>>>(pQh, pQl, pKh, pKl, pS);
    }

    // softmax -> bf16 (hi, lo) probabilities
    softmax_causal_kernel<<<dim3(SEQ, BATCH), t256>>>();

    // feat = P V (tensor cores, K-limited by causality)
    {
        dim3 g(DPROJ / 128, SEQ / 128, BATCH);
        mma_gemm_gen<<<g, t256, QKV_SMEM>>>(pPhi, pPlo, pVh, pVl, nullptr, pF,
                                            DPROJ, SEQ,
                                            (size_t)SEQ * SEQ,
                                            (size_t)SEQ * DPROJ,
                                            (size_t)SEQ * DPROJ, 1);
    }

    pool_kernel<<<BATCH, t256>>>(Wscore, Wp2h, bp2h);

    // split feat-assist (per batch -> contiguous)
    for (int b = 0; b < BATCH; b++)
        split_kernel<<<512, t256>>>(pF + ((size_t)b * SEQ + ASSIST) * DPROJ,
                                    pfah + (size_t)b * RUN * DMEM,
                                    pfal + (size_t)b * RUN * DMEM,
                                    (size_t)RUN * DMEM / 4);
    // pitched splits of Wz|Wr|Wh into combined [512, 1536] and bias concat
    split_pitch_kernel<<<256, t256>>>(Wz, pUwCh,        pUwCl,        DMEM, NG, UWSZ / 4);
    split_pitch_kernel<<<256, t256>>>(Wr, pUwCh + 512,  pUwCl + 512,  DMEM, NG, UWSZ / 4);
    split_pitch_kernel<<<256, t256>>>(Wh, pUwCh + 1024, pUwCl + 1024, DMEM, NG, UWSZ / 4);
    concat_bias_kernel<<<6, t256>>>(bz, br, bh, pbzrh);

    // G = feat_assist @ [Wz|Wr|Wh] + [bz|br|bh]  (ONE launch, N=1536)
    {
        dim3 g(NG / 128, RUN / 128, BATCH);
        size_t aS = (size_t)RUN * DMEM, cS = (size_t)RUN * NG;
        mma_gemm_gen<<<g, t256, QKV_SMEM>>>(pfah, pfal, pUwCh, pUwCl,
                                            (const float*)pbzrh, pG,
                                            NG, DPROJ, aS, 0, cS, 0);
    }

    init_out_kernel<<<(BATCH * RUN + 255) / 256, t256>>>(out, bmem);

    // cluster scan: 4 clusters x 16 CTAs x 512 threads
    cudaFuncSetAttribute(scan_cluster,
                         cudaFuncAttributeMaxDynamicSharedMemorySize, SCAN_SMEM);
    cudaFuncSetAttribute(scan_cluster,
                         cudaFuncAttributeNonPortableClusterSizeAllowed, 1);
    {
        cudaLaunchConfig_t cfg = {};
        cfg.gridDim  = dim3(64, 1, 1);
        cfg.blockDim = dim3(SCAN_THREADS, 1, 1);
        cfg.dynamicSmemBytes = SCAN_SMEM;
        cfg.stream = 0;
        cudaLaunchAttribute attrs[1];
        attrs[0].id = cudaLaunchAttributeClusterDimension;
        attrs[0].val.clusterDim.x = CL;
        attrs[0].val.clusterDim.y = 1;
        attrs[0].val.clusterDim.z = 1;
        cfg.attrs = attrs;
        cfg.numAttrs = 1;
        cudaLaunchKernelEx(&cfg, scan_cluster,
                           Uz, Ur, Uh, Wmem, (const float*)pG, out);
    }

    (void)out_size;
}